// round 5
// baseline (speedup 1.0000x reference)
#include <cuda_runtime.h>
#include <math.h>

#define DEPTH  6
#define DIM    512
#define HEADS  8
#define DH     64
#define NB     266
#define FFD    2048
#define OUTD   32
#define BATCH  4
#define SEQ    8192
#define MROWS  (BATCH*SEQ)   // 32768
#define BH     (BATCH*HEADS) // 32
#define MPAD   320
#define CTXW   80
#define ASTR   68
#define BSTR   332
#define CSTR   88
#define EPSF   1e-4f
#define DN     0.3535533905932738f
#define RATIO  0.06131393394849658f
#define SPLITK 4
#define STG    4

// weight scratch offsets (floats)
#define WQOFF  0
#define WKOFF  (DEPTH*DIM*DIM)
#define WVOFF  (2*DEPTH*DIM*DIM)
#define WOOFF  (3*DEPTH*DIM*DIM)
#define W1OFF  (4*DEPTH*DIM*DIM)
#define W2OFF  (4*DEPTH*DIM*DIM + DEPTH*DIM*FFD)
#define WRTOT  (4*DEPTH*DIM*DIM + 2*DEPTH*DIM*FFD)

// ---------------- scratch ----------------
__device__ __align__(256) float g_x[MROWS*DIM];
__device__ __align__(256) float g_h[MROWS*DIM];
__device__ __align__(256) float g_q[MROWS*DIM];
__device__ __align__(256) float g_k[MROWS*DIM];
__device__ __align__(256) float g_v[MROWS*DIM];
__device__ __align__(256) float g_o[MROWS*DIM];
__device__ __align__(256) float g_ff[MROWS*FFD];
__device__ __align__(256) float g_kpT[(size_t)BH*MPAD*SEQ];
__device__ __align__(256) float g_ctx[BH*MPAD*CTXW];
__device__ __align__(256) float g_diag[BH*SEQ];
__device__ __align__(256) unsigned g_projT[DH*MPAD];
__device__ __align__(256) float g_wr[WRTOT];
__device__ float g_kmax;

// ---------------- helpers ----------------
__device__ __forceinline__ void atomicMaxF(float* addr, float val) {
    int old = __float_as_int(*addr);
    while (__int_as_float(old) < val) {
        int assumed = old;
        old = atomicCAS((int*)addr, assumed, __float_as_int(val));
        if (old == assumed) break;
    }
}

__device__ __forceinline__ float fast_exp(float x) {
    float t = x * 1.4426950408889634f;
    t = fminf(fmaxf(t, -126.0f), 126.0f);
    float z = t + 12582912.0f;
    int n = __float_as_int(z) - 0x4B400000;
    float f = t - (z - 12582912.0f);
    float p = 1.33335581e-3f;
    p = fmaf(p, f, 9.61812911e-3f);
    p = fmaf(p, f, 5.55041087e-2f);
    p = fmaf(p, f, 2.40226507e-1f);
    p = fmaf(p, f, 6.93147181e-1f);
    p = fmaf(p, f, 1.0f);
    return p * __int_as_float((n + 127) << 23);
}

__device__ __forceinline__ float fast_rcp(float x) {
    float y = __int_as_float(0x7EF311C3 - __float_as_int(x));
    y = y * (2.0f - x * y);
    y = y * (2.0f - x * y);
    y = y * (2.0f - x * y);
    return y;
}

__device__ __forceinline__ float gelu_fast(float x) {
    float u = 0.7978845608028654f * (x + 0.044715f * x * x * x);
    u = fminf(fmaxf(u, -9.0f), 9.0f);
    float E = fast_exp(2.0f * u);
    float th = 1.0f - 2.0f * fast_rcp(E + 1.0f);
    return 0.5f * x * (1.0f + th);
}

__device__ __forceinline__ unsigned f2tf32(float x) {
    unsigned r;
    asm("cvt.rna.tf32.f32 %0, %1;" : "=r"(r) : "f"(x));
    return r;
}
__device__ __forceinline__ float rndf(float x) { return __uint_as_float(f2tf32(x)); }

__device__ __forceinline__ void mma_tf32(float (&d)[4], const unsigned (&a)[4], const unsigned (&b)[2]) {
    asm volatile(
        "mma.sync.aligned.m16n8k8.row.col.f32.tf32.tf32.f32 "
        "{%0,%1,%2,%3}, {%4,%5,%6,%7}, {%8,%9}, {%0,%1,%2,%3};\n"
        : "+f"(d[0]), "+f"(d[1]), "+f"(d[2]), "+f"(d[3])
        : "r"(a[0]), "r"(a[1]), "r"(a[2]), "r"(a[3]), "r"(b[0]), "r"(b[1]));
}

__device__ __forceinline__ void cp16(unsigned* s, const void* g) {
    unsigned saddr = (unsigned)__cvta_generic_to_shared(s);
    asm volatile("cp.async.cg.shared.global [%0], [%1], 16;\n" :: "r"(saddr), "l"(g));
}
__device__ __forceinline__ void cp_commit() { asm volatile("cp.async.commit_group;\n"); }
template<int N> __device__ __forceinline__ void cp_wait() {
    asm volatile("cp.async.wait_group %0;\n" :: "n"(N));
}

// ---------------- init / reset / preround ----------------
__global__ void copy_src_kernel(const float* __restrict__ src) {
    int i = blockIdx.x * blockDim.x + threadIdx.x;
    if (i < MROWS*DIM) g_x[i] = src[i];
}

__global__ void reset_kernel() {
    int i = blockIdx.x * blockDim.x + threadIdx.x;
    if (i < BH*MPAD*CTXW) g_ctx[i] = 0.f;
    if (i == 0) g_kmax = __int_as_float(0xff800000);
}

__global__ void round_kernel(const float* __restrict__ src, float* __restrict__ dst, int n4) {
    int i = blockIdx.x * blockDim.x + threadIdx.x;
    if (i < n4) {
        float4 v = ((const float4*)src)[i];
        v.x = rndf(v.x); v.y = rndf(v.y); v.z = rndf(v.z); v.w = rndf(v.w);
        ((float4*)dst)[i] = v;
    }
}

__global__ void projt_kernel(const float* __restrict__ proj) {
    int i = blockIdx.x * blockDim.x + threadIdx.x;
    if (i < DH*MPAD) {
        int d = i / MPAD, f = i % MPAD;
        float v = (f < NB) ? proj[f*DH + d] : 0.f;
        g_projT[i] = f2tf32(v);
    }
}

// ---------------- LayerNorm (output rounded to tf32 grid) ----------------
__global__ void __launch_bounds__(128) ln_kernel(
    const float* __restrict__ x, const float* __restrict__ g,
    const float* __restrict__ b, float* __restrict__ o)
{
    int row = blockIdx.x, tid = threadIdx.x, lane = tid & 31, w = tid >> 5;
    const float4 xv = ((const float4*)(x + (size_t)row*DIM))[tid];
    float s = xv.x + xv.y + xv.z + xv.w;
    float q = xv.x*xv.x + xv.y*xv.y + xv.z*xv.z + xv.w*xv.w;
    #pragma unroll
    for (int off = 16; off; off >>= 1) {
        s += __shfl_xor_sync(0xffffffffu, s, off);
        q += __shfl_xor_sync(0xffffffffu, q, off);
    }
    __shared__ float ss[4], sq[4];
    if (lane == 0) { ss[w] = s; sq[w] = q; }
    __syncthreads();
    float S = ss[0]+ss[1]+ss[2]+ss[3];
    float Q = sq[0]+sq[1]+sq[2]+sq[3];
    float mean = S * (1.0f/DIM);
    float var  = Q * (1.0f/DIM) - mean*mean;
    float inv  = rsqrtf(var + 1e-5f);
    float4 gv = ((const float4*)g)[tid];
    float4 bv = ((const float4*)b)[tid];
    float4 ov;
    ov.x = rndf((xv.x - mean)*inv*gv.x + bv.x);
    ov.y = rndf((xv.y - mean)*inv*gv.y + bv.y);
    ov.z = rndf((xv.z - mean)*inv*gv.z + bv.z);
    ov.w = rndf((xv.w - mean)*inv*gv.w + bv.w);
    ((float4*)(o + (size_t)row*DIM))[tid] = ov;
}

// ---------------- TF32 GEMM, cp.async 4-stage, warp tile 64x64 ----------------
// 128 threads = 4 warps (2x2). CTA tile 128x128x16. Inputs must be tf32-grid values.
template<int BIASF, int RESF, int GELUF, int ROUNDF>
__global__ void __launch_bounds__(128, 2) tgemm_kernel(
    const float* __restrict__ A, const float* __restrict__ W,
    const float* __restrict__ bias, const float* __restrict__ res,
    float* __restrict__ C, int M, int N, int K)
{
    extern __shared__ unsigned smu[];
    const int ASZ = 128*20, BSZ = 16*136;
    unsigned* As = smu;
    unsigned* Bs = smu + STG*ASZ;

    const int tid = threadIdx.x, lane = tid & 31, warp = tid >> 5;
    const int wm = warp >> 1, wn = warp & 1;
    const int qg = lane >> 2, qt = lane & 3;
    const float* Ab = A + (size_t)(blockIdx.y*128)*K;
    const float* Wb = W + blockIdx.x*128;

    const int ar = tid >> 2, ac = (tid & 3) * 4;   // A rows ar+32g
    const int br = tid >> 5, bc = (tid & 31) * 4;  // B rows br+4g

    float acc[4][8][4];
    #pragma unroll
    for (int i = 0; i < 4; i++)
        #pragma unroll
        for (int j = 0; j < 8; j++)
            #pragma unroll
            for (int r = 0; r < 4; r++) acc[i][j][r] = 0.f;

    const int ntiles = K >> 4;

    #pragma unroll
    for (int s = 0; s < STG-1; s++) {
        unsigned* Ad = As + s*ASZ;
        unsigned* Bd = Bs + s*BSZ;
        const int ko = s*16;
        #pragma unroll
        for (int g = 0; g < 4; g++)
            cp16(Ad + (ar + 32*g)*20 + ac, Ab + (size_t)(ar + 32*g)*K + ko + ac);
        #pragma unroll
        for (int g = 0; g < 4; g++)
            cp16(Bd + (br + 4*g)*136 + bc, Wb + (size_t)(ko + br + 4*g)*N + bc);
        cp_commit();
    }
    cp_wait<STG-2>();
    __syncthreads();

    #pragma unroll 1
    for (int kt = 0; kt < ntiles; kt++) {
        const int stg = kt & (STG-1);
        if (kt + STG-1 < ntiles) {
            const int ns = (kt + STG-1) & (STG-1);
            unsigned* Ad = As + ns*ASZ;
            unsigned* Bd = Bs + ns*BSZ;
            const int ko = (kt + STG-1) * 16;
            #pragma unroll
            for (int g = 0; g < 4; g++)
                cp16(Ad + (ar + 32*g)*20 + ac, Ab + (size_t)(ar + 32*g)*K + ko + ac);
            #pragma unroll
            for (int g = 0; g < 4; g++)
                cp16(Bd + (br + 4*g)*136 + bc, Wb + (size_t)(ko + br + 4*g)*N + bc);
        }
        cp_commit();

        const unsigned* At = As + stg*ASZ;
        const unsigned* Bt = Bs + stg*BSZ;
        #pragma unroll
        for (int kk = 0; kk < 16; kk += 8) {
            unsigned af[4][4], bf[8][2];
            #pragma unroll
            for (int i = 0; i < 4; i++) {
                const unsigned* ap = At + (wm*64 + i*16 + qg)*20 + kk + qt;
                af[i][0] = ap[0];
                af[i][1] = ap[8*20];
                af[i][2] = ap[4];
                af[i][3] = ap[8*20 + 4];
            }
            #pragma unroll
            for (int j = 0; j < 8; j++) {
                const unsigned* bp = Bt + (kk + qt)*136 + wn*64 + j*8 + qg;
                bf[j][0] = bp[0];
                bf[j][1] = bp[4*136];
            }
            #pragma unroll
            for (int i = 0; i < 4; i++)
                #pragma unroll
                for (int j = 0; j < 8; j++)
                    mma_tf32(acc[i][j], af[i], bf[j]);
        }
        cp_wait<STG-2>();
        __syncthreads();
    }

    const int row0 = blockIdx.y*128 + wm*64;
    const int col0 = blockIdx.x*128 + wn*64;
    #pragma unroll
    for (int i = 0; i < 4; i++) {
        #pragma unroll
        for (int j = 0; j < 8; j++) {
            int r = row0 + i*16 + qg;
            int c = col0 + j*8 + qt*2;
            float b0 = 0.f, b1 = 0.f;
            if (BIASF) { b0 = bias[c]; b1 = bias[c+1]; }
            float v0 = acc[i][j][0] + b0;
            float v1 = acc[i][j][1] + b1;
            float v2 = acc[i][j][2] + b0;
            float v3 = acc[i][j][3] + b1;
            if (GELUF) { v0 = gelu_fast(v0); v1 = gelu_fast(v1); v2 = gelu_fast(v2); v3 = gelu_fast(v3); }
            if (RESF) {
                const float2 r0v = *(const float2*)(res + (size_t)r*N + c);
                const float2 r1v = *(const float2*)(res + (size_t)(r+8)*N + c);
                v0 += r0v.x; v1 += r0v.y; v2 += r1v.x; v3 += r1v.y;
            }
            if (ROUNDF) { v0 = rndf(v0); v1 = rndf(v1); v2 = rndf(v2); v3 = rndf(v3); }
            *(float2*)(C + (size_t)r*N + c)     = make_float2(v0, v1);
            *(float2*)(C + (size_t)(r+8)*N + c) = make_float2(v2, v3);
        }
    }
}

// ---------------- feature-map kernels (TF32 MMA) ----------------
template<int ISQ>
__global__ void __launch_bounds__(256) xfeat_kernel()
{
    extern __shared__ unsigned smu[];
    unsigned* As = smu;
    unsigned* Bs = As + 64*ASTR;
    unsigned* Cs = Bs + 64*BSTR;
    float* s_aux = (float*)(ISQ ? (Cs + MPAD*CSTR) : Cs);
    float* s_diag = s_aux;
    float* s_rmax = s_diag + 64;
    float* s_dnm  = s_rmax + 256;
    float* s_wm   = s_dnm + 64;

    const int tid = threadIdx.x, lane = tid & 31, warp = tid >> 5;
    const int qg = lane >> 2, qt = lane & 3;
    const int wm = warp >> 2, wn = warp & 3;
    const int bh = blockIdx.y, b = bh >> 3, hh = bh & 7;
    const int n0 = blockIdx.x * 64;
    const float* src = (ISQ ? g_q : g_k) + ((size_t)b*SEQ + n0)*DIM + hh*DH;

    #pragma unroll
    for (int i = tid; i < 64*16; i += 256) {
        int r = i >> 4, c4 = (i & 15) * 4;
        float4 v = *(const float4*)(src + (size_t)r*DIM + c4);
        As[r*ASTR + c4+0] = f2tf32(v.x*DN);
        As[r*ASTR + c4+1] = f2tf32(v.y*DN);
        As[r*ASTR + c4+2] = f2tf32(v.z*DN);
        As[r*ASTR + c4+3] = f2tf32(v.w*DN);
    }
    #pragma unroll
    for (int i = tid; i < 64*80; i += 256) {
        int r = i / 80, c4 = (i % 80) * 4;
        uint4 v = *(const uint4*)(g_projT + r*MPAD + c4);
        Bs[r*BSTR + c4+0] = v.x;
        Bs[r*BSTR + c4+1] = v.y;
        Bs[r*BSTR + c4+2] = v.z;
        Bs[r*BSTR + c4+3] = v.w;
    }
    if (ISQ) {
        const float* cb = g_ctx + (size_t)bh*MPAD*CTXW;
        #pragma unroll
        for (int i = tid; i < MPAD*20; i += 256) {
            int r = i / 20, c4 = (i % 20) * 4;
            float4 v = *(const float4*)(cb + r*CTXW + c4);
            Cs[r*CSTR + c4+0] = f2tf32(v.x);
            Cs[r*CSTR + c4+1] = f2tf32(v.y);
            Cs[r*CSTR + c4+2] = f2tf32(v.z);
            Cs[r*CSTR + c4+3] = f2tf32(v.w);
        }
    }
    __syncthreads();

    if (tid < 64) {
        float s = 0.f;
        #pragma unroll 16
        for (int d = 0; d < DH; d++) {
            float v = __uint_as_float(As[tid*ASTR + d]);
            s += v*v;
        }
        s = 0.5f * s;
        s_diag[tid] = s;
        if (!ISQ) g_diag[(size_t)bh*SEQ + n0 + tid] = s;
    }

    float acc1[2][10][4];
    #pragma unroll
    for (int i = 0; i < 2; i++)
        #pragma unroll
        for (int j = 0; j < 10; j++)
            #pragma unroll
            for (int r = 0; r < 4; r++) acc1[i][j][r] = 0.f;

    #pragma unroll
    for (int kk = 0; kk < 64; kk += 8) {
        unsigned af[2][4], bf[10][2];
        #pragma unroll
        for (int i = 0; i < 2; i++) {
            const unsigned* ap = As + (wm*32 + i*16 + qg)*ASTR + kk + qt;
            af[i][0] = ap[0];
            af[i][1] = ap[8*ASTR];
            af[i][2] = ap[4];
            af[i][3] = ap[8*ASTR + 4];
        }
        #pragma unroll
        for (int j = 0; j < 10; j++) {
            const unsigned* bp = Bs + (kk + qt)*BSTR + wn*80 + j*8 + qg;
            bf[j][0] = bp[0];
            bf[j][1] = bp[4*BSTR];
        }
        #pragma unroll
        for (int i = 0; i < 2; i++)
            #pragma unroll
            for (int j = 0; j < 10; j++)
                mma_tf32(acc1[i][j], af[i], bf[j]);
    }

    float* fBs = (float*)Bs;

    if (!ISQ) {
        float m = __int_as_float(0xff800000);
        #pragma unroll
        for (int i = 0; i < 2; i++)
            #pragma unroll
            for (int j = 0; j < 10; j++)
                #pragma unroll
                for (int r = 0; r < 4; r++) {
                    int col = wn*80 + j*8 + qt*2 + (r & 1);
                    if (col < NB) m = fmaxf(m, acc1[i][j][r]);
                }
        #pragma unroll
        for (int off = 16; off; off >>= 1) m = fmaxf(m, __shfl_xor_sync(0xffffffffu, m, off));
        if (lane == 0) s_wm[warp] = m;
        __syncthreads();
        if (tid == 0) {
            float mm = s_wm[0];
            #pragma unroll
            for (int i = 1; i < 8; i++) mm = fmaxf(mm, s_wm[i]);
            atomicMaxF(&g_kmax, mm);
        }
        #pragma unroll
        for (int i = 0; i < 2; i++)
            #pragma unroll
            for (int j = 0; j < 10; j++)
                #pragma unroll
                for (int r = 0; r < 4; r++) {
                    int row = wm*32 + i*16 + qg + 8*(r >> 1);
                    int col = wn*80 + j*8 + qt*2 + (r & 1);
                    fBs[row*BSTR + col] = (col < NB) ? acc1[i][j][r] : 0.f;
                }
        __syncthreads();
        #pragma unroll
        for (int i = tid; i < 64*80; i += 256) {
            int n = i & 63, f4 = (i >> 6) * 4;
            float4 v = *(const float4*)&fBs[n*BSTR + f4];
            float* dst = g_kpT + ((size_t)bh*MPAD + f4)*SEQ + n0 + n;
            dst[0]      = v.x;
            dst[SEQ]    = v.y;
            dst[2*SEQ]  = v.z;
            dst[3*SEQ]  = v.w;
        }
        return;
    }

    // rowmax
    #pragma unroll
    for (int i = 0; i < 2; i++) {
        #pragma unroll
        for (int h = 0; h < 2; h++) {
            float m = __int_as_float(0xff800000);
            #pragma unroll
            for (int j = 0; j < 10; j++) {
                #pragma unroll
                for (int rb = 0; rb < 2; rb++) {
                    int col = wn*80 + j*8 + qt*2 + rb;
                    if (col < NB) m = fmaxf(m, acc1[i][j][2*h + rb]);
                }
            }
            m = fmaxf(m, __shfl_xor_sync(0xffffffffu, m, 1));
            m = fmaxf(m, __shfl_xor_sync(0xffffffffu, m, 2));
            if (qt == 0) s_rmax[(wm*32 + i*16 + qg + 8*h)*4 + wn] = m;
        }
    }
    __syncthreads();

    float sub[2][2];
    #pragma unroll
    for (int i = 0; i < 2; i++)
        #pragma unroll
        for (int h = 0; h < 2; h++) {
            int row = wm*32 + i*16 + qg + 8*h;
            float m = fmaxf(fmaxf(s_rmax[row*4+0], s_rmax[row*4+1]),
                            fmaxf(s_rmax[row*4+2], s_rmax[row*4+3]));
            sub[i][h] = m + s_diag[row];
        }
    #pragma unroll
    for (int i = 0; i < 2; i++)
        #pragma unroll
        for (int j = 0; j < 10; j++)
            #pragma unroll
            for (int r = 0; r < 4; r++) {
                int row = wm*32 + i*16 + qg + 8*(r >> 1);
                int col = wn*80 + j*8 + qt*2 + (r & 1);
                float v = 0.f;
                if (col < NB) v = RATIO * (fast_exp(acc1[i][j][r] - sub[i][r >> 1]) + EPSF);
                Bs[row*BSTR + col] = f2tf32(v);
            }
    __syncthreads();

    const int wm2 = warp >> 1, wn2 = warp & 1;
    float acc2[5][4];
    #pragma unroll
    for (int j = 0; j < 5; j++)
        #pragma unroll
        for (int r = 0; r < 4; r++) acc2[j][r] = 0.f;

    #pragma unroll 4
    for (int kk = 0; kk < MPAD; kk += 8) {
        unsigned af[4], bf[5][2];
        const unsigned* ap = Bs + (wm2*16 + qg)*BSTR + kk + qt;
        af[0] = ap[0];
        af[1] = ap[8*BSTR];
        af[2] = ap[4];
        af[3] = ap[8*BSTR + 4];
        #pragma unroll
        for (int j = 0; j < 5; j++) {
            const unsigned* bp = Cs + (kk + qt)*CSTR + wn2*40 + j*8 + qg;
            bf[j][0] = bp[0];
            bf[j][1] = bp[4*CSTR];
        }
        #pragma unroll
        for (int j = 0; j < 5; j++)
            mma_tf32(acc2[j], af, bf[j]);
    }

    #pragma unroll
    for (int j = 0; j < 5; j++)
        #pragma unroll
        for (int r = 0; r < 4; r++) {
            int col = wn2*40 + j*8 + qt*2 + (r & 1);
            if (col == 64) {
                int row = wm2*16 + qg + 8*(r >> 1);
                s_dnm[row] = acc2[j][r];
            }
        }
    __syncthreads();

    float invd0 = 1.0f / s_dnm[wm2*16 + qg];
    float invd1 = 1.0f / s_dnm[wm2*16 + qg + 8];
    float* ob = g_o + ((size_t)b*SEQ + n0)*DIM + hh*DH;
    #pragma unroll
    for (int j = 0; j < 5; j++)
        #pragma unroll
        for (int r = 0; r < 4; r++) {
            int col = wn2*40 + j*8 + qt*2 + (r & 1);
            if (col < 64) {
                int row = wm2*16 + qg + 8*(r >> 1);
                ob[(size_t)row*DIM + col] = rndf(acc2[j][r] * ((r >> 1) ? invd1 : invd0));
            }
        }
}

// ---------------- ctx (exp fused, rna-rounded operands) ----------------
__global__ void __launch_bounds__(256) ctx_kernel()
{
    __shared__ unsigned As[64*ASTR];
    __shared__ unsigned Bs[64*CSTR];
    const int tid = threadIdx.x, lane = tid & 31, warp = tid >> 5;
    const int qg = lane >> 2, qt = lane & 3;
    const int wm = warp >> 1, wn = warp & 1;
    const int f0 = blockIdx.x * 64, bh = blockIdx.y, b = bh >> 3, hh = bh & 7;
    const int nbase = blockIdx.z * (SEQ / SPLITK);
    const float km = g_kmax;

    if (tid < 64) {
        Bs[tid*CSTR + 64] = 0x3f800000u;
        #pragma unroll
        for (int c = 65; c < 80; c++) Bs[tid*CSTR + c] = 0u;
    }

    float acc[5][4];
    #pragma unroll
    for (int j = 0; j < 5; j++)
        #pragma unroll
        for (int r = 0; r < 4; r++) acc[j][r] = 0.f;

    for (int ch = 0; ch < SEQ/SPLITK; ch += 64) {
        __syncthreads();
        const int n0 = nbase + ch;
        #pragma unroll
        for (int i = tid; i < 1024; i += 256) {
            int f = i >> 4, n4 = (i & 15) * 4;
            float4 v  = *(const float4*)(g_kpT + ((size_t)bh*MPAD + f0 + f)*SEQ + n0 + n4);
            float4 dg = *(const float4*)(g_diag + (size_t)bh*SEQ + n0 + n4);
            unsigned* ap = As + f*ASTR + n4;
            ap[0] = f2tf32(RATIO * (fast_exp(v.x - dg.x - km) + EPSF));
            ap[1] = f2tf32(RATIO * (fast_exp(v.y - dg.y - km) + EPSF));
            ap[2] = f2tf32(RATIO * (fast_exp(v.z - dg.z - km) + EPSF));
            ap[3] = f2tf32(RATIO * (fast_exp(v.w - dg.w - km) + EPSF));
        }
        #pragma unroll
        for (int i = tid; i < 1024; i += 256) {
            int n = i >> 4, d4 = (i & 15) * 4;
            float4 v = *(const float4*)(g_v + ((size_t)b*SEQ + n0 + n)*DIM + hh*DH + d4);
            unsigned* bp = Bs + n*CSTR + d4;
            bp[0] = __float_as_uint(v.x);
            bp[1] = __float_as_uint(v.y);
            bp[2] = __float_as_uint(v.z);
            bp[3] = __float_as_uint(v.w);
        }
        __syncthreads();
        #pragma unroll
        for (int kk = 0; kk < 64; kk += 8) {
            unsigned af[4], bf[5][2];
            const unsigned* ap = As + (wm*16 + qg)*ASTR + kk + qt;
            af[0] = ap[0];
            af[1] = ap[8*ASTR];
            af[2] = ap[4];
            af[3] = ap[8*ASTR + 4];
            #pragma unroll
            for (int j = 0; j < 5; j++) {
                const unsigned* bp = Bs + (kk + qt)*CSTR + wn*40 + j*8 + qg;
                bf[j][0] = bp[0];
                bf[j][1] = bp[4*CSTR];
            }
            #pragma unroll
            for (int j = 0; j < 5; j++)
                mma_tf32(acc[j], af, bf[j]);
        }
    }

    float* cb = g_ctx + (size_t)bh*MPAD*CTXW;
    #pragma unroll
    for (int j = 0; j < 5; j++)
        #pragma unroll
        for (int r = 0; r < 4; r++) {
            int row = wm*16 + qg + 8*(r >> 1);
            int col = wn*40 + j*8 + qt*2 + (r & 1);
            if (col < 65)
                atomicAdd(&cb[(f0 + row)*CTXW + col], acc[j][r]);
        }
}

// ---------------- final fc ----------------
__global__ void __launch_bounds__(256) fc_kernel(
    const float* __restrict__ x, const float* __restrict__ w,
    const float* __restrict__ bias, float* __restrict__ out)
{
    __shared__ float xs[8*DIM];
    int tid = threadIdx.x;
    int m0 = blockIdx.x * 8;
    for (int i = tid; i < 8*DIM/4; i += 256)
        ((float4*)xs)[i] = ((const float4*)(x + (size_t)m0*DIM))[i];
    __syncthreads();
    int r = tid >> 5, c = tid & 31;
    float acc = 0.f;
    const float* xr = &xs[r*DIM];
    #pragma unroll 8
    for (int k = 0; k < DIM; k++) acc += xr[k] * w[k*OUTD + c];
    out[(size_t)(m0 + r)*OUTD + c] = acc + bias[c];
}

// ---------------- host launcher ----------------
extern "C" void kernel_launch(void* const* d_in, const int* in_sizes, int n_in,
                              void* d_out, int out_size)
{
    (void)in_sizes; (void)n_in; (void)out_size;
    const float* src  = (const float*)d_in[0];
    const float* proj = (const float*)d_in[1];
    const float* ln1g = (const float*)d_in[2];
    const float* ln1b = (const float*)d_in[3];
    const float* Wq   = (const float*)d_in[4];
    const float* Wk   = (const float*)d_in[5];
    const float* Wv   = (const float*)d_in[6];
    const float* Wo   = (const float*)d_in[7];
    const float* bo   = (const float*)d_in[8];
    const float* ln2g = (const float*)d_in[9];
    const float* ln2b = (const float*)d_in[10];
    const float* W1   = (const float*)d_in[11];
    const float* b1   = (const float*)d_in[12];
    const float* W2   = (const float*)d_in[13];
    const float* b2   = (const float*)d_in[14];
    const float* fcw  = (const float*)d_in[15];
    const float* fcb  = (const float*)d_in[16];
    float* out = (float*)d_out;

    float *xp, *hp, *qb, *kb, *vb, *ob, *ffb, *wr;
    cudaGetSymbolAddress((void**)&xp,  g_x);
    cudaGetSymbolAddress((void**)&hp,  g_h);
    cudaGetSymbolAddress((void**)&qb,  g_q);
    cudaGetSymbolAddress((void**)&kb,  g_k);
    cudaGetSymbolAddress((void**)&vb,  g_v);
    cudaGetSymbolAddress((void**)&ob,  g_o);
    cudaGetSymbolAddress((void**)&ffb, g_ff);
    cudaGetSymbolAddress((void**)&wr,  g_wr);

    const int gemm_smem = STG*(128*20 + 16*136)*4;  // 75776
    cudaFuncSetAttribute(tgemm_kernel<0,0,0,1>, cudaFuncAttributeMaxDynamicSharedMemorySize, gemm_smem);
    cudaFuncSetAttribute(tgemm_kernel<1,1,0,0>, cudaFuncAttributeMaxDynamicSharedMemorySize, gemm_smem);
    cudaFuncSetAttribute(tgemm_kernel<1,0,1,1>, cudaFuncAttributeMaxDynamicSharedMemorySize, gemm_smem);

    const int xk_smem = (64*ASTR + 64*BSTR)*4 + (64 + 256 + 64 + 8)*4;
    const int xq_smem = (64*ASTR + 64*BSTR + MPAD*CSTR)*4 + (64 + 256 + 64 + 8)*4;
    cudaFuncSetAttribute(xfeat_kernel<0>, cudaFuncAttributeMaxDynamicSharedMemorySize, xk_smem);
    cudaFuncSetAttribute(xfeat_kernel<1>, cudaFuncAttributeMaxDynamicSharedMemorySize, xq_smem);

    copy_src_kernel<<<(MROWS*DIM + 255)/256, 256>>>(src);

    // pre-round all weights to tf32 grid (rna)
    const int QW4 = DEPTH*DIM*DIM/4, FW4 = DEPTH*DIM*FFD/4;
    round_kernel<<<(QW4 + 255)/256, 256>>>(Wq, wr + WQOFF, QW4);
    round_kernel<<<(QW4 + 255)/256, 256>>>(Wk, wr + WKOFF, QW4);
    round_kernel<<<(QW4 + 255)/256, 256>>>(Wv, wr + WVOFF, QW4);
    round_kernel<<<(QW4 + 255)/256, 256>>>(Wo, wr + WOOFF, QW4);
    round_kernel<<<(FW4 + 255)/256, 256>>>(W1, wr + W1OFF, FW4);
    round_kernel<<<(FW4 + 255)/256, 256>>>(W2, wr + W2OFF, FW4);

    dim3 gg(DIM/128, MROWS/128);
    dim3 gf(FFD/128, MROWS/128);
    dim3 xg(SEQ/64, BH);

    for (int L = 0; L < DEPTH; L++) {
        ln_kernel<<<MROWS, 128>>>(xp, ln1g + L*DIM, ln1b + L*DIM, hp);
        tgemm_kernel<0,0,0,1><<<gg, 128, gemm_smem>>>(hp, wr + WQOFF + (size_t)L*DIM*DIM, 0, 0, qb, MROWS, DIM, DIM);
        tgemm_kernel<0,0,0,1><<<gg, 128, gemm_smem>>>(hp, wr + WKOFF + (size_t)L*DIM*DIM, 0, 0, kb, MROWS, DIM, DIM);
        tgemm_kernel<0,0,0,1><<<gg, 128, gemm_smem>>>(hp, wr + WVOFF + (size_t)L*DIM*DIM, 0, 0, vb, MROWS, DIM, DIM);
        projt_kernel<<<(DH*MPAD + 255)/256, 256>>>(proj + (size_t)L*NB*DH);
        reset_kernel<<<(BH*MPAD*CTXW + 255)/256, 256>>>();
        xfeat_kernel<0><<<xg, 256, xk_smem>>>();
        ctx_kernel<<<dim3(MPAD/64, BH, SPLITK), 256>>>();
        xfeat_kernel<1><<<xg, 256, xq_smem>>>();
        tgemm_kernel<1,1,0,0><<<gg, 128, gemm_smem>>>(ob, wr + WOOFF + (size_t)L*DIM*DIM, bo + L*DIM, xp, xp, MROWS, DIM, DIM);
        ln_kernel<<<MROWS, 128>>>(xp, ln2g + L*DIM, ln2b + L*DIM, hp);
        tgemm_kernel<1,0,1,1><<<gf, 128, gemm_smem>>>(hp, wr + W1OFF + (size_t)L*DIM*FFD, b1 + L*FFD, 0, ffb, MROWS, FFD, DIM);
        tgemm_kernel<1,1,0,0><<<gg, 128, gemm_smem>>>(ffb, wr + W2OFF + (size_t)L*FFD*DIM, b2 + L*DIM, xp, xp, MROWS, DIM, FFD);
    }
    fc_kernel<<<MROWS/8, 256>>>(xp, fcw, fcb, out);
}